// round 10
// baseline (speedup 1.0000x reference)
#include <cuda_runtime.h>
#include <math.h>

#define BETA 0.1f

// FINAL: one block per (b,p) tile, 256 threads.
// De-interleaved store phase (best measured config, 41.6us kernel):
// warps 0-3 (tid 0..127) write the whole `places` tile; warps 4-7 write the
// whole `sampled` tile. Each half-block covers 1024 float4 in 8 coalesced
// iterations. Kernel is at the HBM3e write-stream roofline (~5.2 TB/s).
__global__ __launch_bounds__(256, 8)
void spatial_sampler_kernel(const float* __restrict__ x_cat,
                            const float* __restrict__ noise,
                            float* __restrict__ out,
                            long long half_elems)
{
    __shared__ float sx[128];   // [0:64) h row, [64:128) v row
    __shared__ float ss[128];   // masked rows (h part pre-scaled by 100)
    __shared__ float wmax[4];

    const int bp  = blockIdx.x;
    const int tid = threadIdx.x;

    const float* xrow = x_cat + (long long)bp * 128;
    const float* nrow = noise + (long long)bp * 128;

    // --- load + log_pdf + per-row max (each 64-wide row = 2 warps) ---
    float lp = -INFINITY;
    float xv = 0.f;
    if (tid < 128) {
        xv = xrow[tid];
        lp = logf(xv) + BETA * nrow[tid];
        sx[tid] = xv;
    }
    float m = lp;
    #pragma unroll
    for (int off = 16; off > 0; off >>= 1)
        m = fmaxf(m, __shfl_xor_sync(0xffffffffu, m, off));
    if (tid < 128 && (tid & 31) == 0)
        wmax[tid >> 5] = m;
    __syncthreads();

    if (tid < 128) {
        float rowmax = (tid < 64) ? fmaxf(wmax[0], wmax[1])
                                  : fmaxf(wmax[2], wmax[3]);
        float s = (lp == rowmax) ? xv : 0.f;
        ss[tid] = (tid < 64) ? s * 100.0f : s;   // fold *100 into h half
    }
    __syncthreads();

    // --- de-interleaved stores: half-block per output tensor ---
    const int  half_tid = tid & 127;          // 0..127 within half-block
    const bool is_samp  = (tid >= 128);

    const float* hsrc = is_samp ? ss      : sx;
    const float4* v4  = reinterpret_cast<const float4*>(is_samp ? &ss[64] : &sx[64]);
    float4* dst = reinterpret_cast<float4*>(
        out + (is_samp ? half_elems : 0) + (long long)bp * 4096);

    #pragma unroll
    for (int it = 0; it < 8; ++it) {
        const int i  = half_tid + it * 128;   // float4 index 0..1023
        const int j  = i >> 4;                // row 0..63
        const int c4 = i & 15;                // float4 col 0..15

        const float hj = hsrc[j];
        float4 vv = v4[c4];
        float4 o;
        o.x = hj * vv.x; o.y = hj * vv.y; o.z = hj * vv.z; o.w = hj * vv.w;
        dst[i] = o;
    }
}

extern "C" void kernel_launch(void* const* d_in, const int* in_sizes, int n_in,
                              void* d_out, int out_size)
{
    const float* x_cat = (const float*)d_in[0];
    const float* noise = (const float*)d_in[1];
    float* out = (float*)d_out;

    const long long half = (long long)out_size / 2;
    const int tiles = in_sizes[0] / 128;   // 8192 (b,p) tiles

    spatial_sampler_kernel<<<tiles, 256>>>(x_cat, noise, out, half);
}

// round 12
// speedup vs baseline: 1.0056x; 1.0056x over previous
#include <cuda_runtime.h>
#include <math.h>

#define BETA 0.1f

// One block per (b,p)-tile PAIR, 512 threads.
// Tiles 2t and 2t+1 are adjacent in each output region, so each half-block
// (256 threads) emits one 32 KB CONTIGUOUS burst into its tensor:
//   tid[0..255]   -> places[2t .. 2t+1]   (32 KB contiguous)
//   tid[256..511] -> sampled[2t .. 2t+1]  (32 KB contiguous)
// Compute phase: threads 0..255 handle the 2x128 input rows (128 per tile).
__global__ __launch_bounds__(512, 4)
void spatial_sampler_kernel(const float* __restrict__ x_cat,
                            const float* __restrict__ noise,
                            float* __restrict__ out,
                            long long half_elems)
{
    __shared__ float sx[2][128];   // [tile][0:64) h, [64:128) v
    __shared__ float ss[2][128];   // masked rows (h half pre-scaled by 100)
    __shared__ float wmax[8];      // per-warp maxima (2 tiles x 4 warps)

    const int tp  = blockIdx.x;          // tile-pair id 0..4095
    const int tid = threadIdx.x;

    // --- compute phase: threads 0..255 = 2 tiles x 128 lanes ---
    if (tid < 256) {
        const int t   = tid >> 7;        // which tile of the pair
        const int r   = tid & 127;       // lane within tile
        const long long base = ((long long)tp * 2 + t) * 128;

        const float xv = x_cat[base + r];
        const float lp = logf(xv) + BETA * noise[base + r];
        sx[t][r] = xv;

        float m = lp;
        #pragma unroll
        for (int off = 16; off > 0; off >>= 1)
            m = fmaxf(m, __shfl_xor_sync(0xffffffffu, m, off));
        if ((tid & 31) == 0) wmax[tid >> 5] = m;
        __syncthreads();

        const int wb = t * 4;            // this tile's warp-max base
        const float rowmax = (r < 64) ? fmaxf(wmax[wb + 0], wmax[wb + 1])
                                      : fmaxf(wmax[wb + 2], wmax[wb + 3]);
        float s = (lp == rowmax) ? xv : 0.f;
        ss[t][r] = (r < 64) ? s * 100.0f : s;   // fold *100 into h half
    } else {
        __syncthreads();
    }
    __syncthreads();

    // --- store phase: half-block per tensor, 32 KB contiguous burst each ---
    const int  half_tid = tid & 255;     // 0..255 within half-block
    const bool is_samp  = (tid >= 256);

    const float (*h2)[128] = is_samp ? ss : sx;
    float4* dst = reinterpret_cast<float4*>(
        out + (is_samp ? half_elems : 0) + (long long)tp * 8192);

    #pragma unroll
    for (int it = 0; it < 8; ++it) {
        const int i  = half_tid + it * 256;   // float4 index 0..2047 (2 tiles)
        const int t  = i >> 10;               // tile of the pair
        const int ii = i & 1023;              // float4 index within tile
        const int j  = ii >> 4;               // row 0..63
        const int c4 = ii & 15;               // float4 col 0..15

        const float hj = h2[t][j];
        const float4* v4 = reinterpret_cast<const float4*>(&h2[t][64]);
        float4 vv = v4[c4];
        float4 o;
        o.x = hj * vv.x; o.y = hj * vv.y; o.z = hj * vv.z; o.w = hj * vv.w;
        dst[i] = o;
    }
}

extern "C" void kernel_launch(void* const* d_in, const int* in_sizes, int n_in,
                              void* d_out, int out_size)
{
    const float* x_cat = (const float*)d_in[0];
    const float* noise = (const float*)d_in[1];
    float* out = (float*)d_out;

    const long long half = (long long)out_size / 2;
    const int tiles = in_sizes[0] / 128;   // 8192
    spatial_sampler_kernel<<<tiles / 2, 512>>>(x_cat, noise, out, half);
}

// round 14
// speedup vs baseline: 1.0126x; 1.0070x over previous
#include <cuda_runtime.h>
#include <math.h>

#define BETA 0.1f

// FINAL (best measured config, 41.6us kernel, 2x reproduced):
// one block per (b,p) tile, 256 threads, de-interleaved store phase:
// warps 0-3 (tid 0..127) write the whole `places` tile; warps 4-7 write the
// whole `sampled` tile; 1024 float4 per half-block in 8 coalesced iterations.
// Kernel is at the HBM3e write-stream roofline (~5.2 TB/s sustained); all
// other levers (store width/path, L2 policy, grid shape, burst length)
// measured neutral across 12 rounds.
__global__ __launch_bounds__(256, 8)
void spatial_sampler_kernel(const float* __restrict__ x_cat,
                            const float* __restrict__ noise,
                            float* __restrict__ out,
                            long long half_elems)
{
    __shared__ float sx[128];   // [0:64) h row, [64:128) v row
    __shared__ float ss[128];   // masked rows (h part pre-scaled by 100)
    __shared__ float wmax[4];

    const int bp  = blockIdx.x;
    const int tid = threadIdx.x;

    const float* xrow = x_cat + (long long)bp * 128;
    const float* nrow = noise + (long long)bp * 128;

    // --- load + log_pdf + per-row max (each 64-wide row = 2 warps) ---
    float lp = -INFINITY;
    float xv = 0.f;
    if (tid < 128) {
        xv = xrow[tid];
        lp = logf(xv) + BETA * nrow[tid];
        sx[tid] = xv;
    }
    float m = lp;
    #pragma unroll
    for (int off = 16; off > 0; off >>= 1)
        m = fmaxf(m, __shfl_xor_sync(0xffffffffu, m, off));
    if (tid < 128 && (tid & 31) == 0)
        wmax[tid >> 5] = m;
    __syncthreads();

    if (tid < 128) {
        float rowmax = (tid < 64) ? fmaxf(wmax[0], wmax[1])
                                  : fmaxf(wmax[2], wmax[3]);
        float s = (lp == rowmax) ? xv : 0.f;
        ss[tid] = (tid < 64) ? s * 100.0f : s;   // fold *100 into h half
    }
    __syncthreads();

    // --- de-interleaved stores: half-block per output tensor ---
    const int  half_tid = tid & 127;          // 0..127 within half-block
    const bool is_samp  = (tid >= 128);

    const float* hsrc = is_samp ? ss      : sx;
    const float4* v4  = reinterpret_cast<const float4*>(is_samp ? &ss[64] : &sx[64]);
    float4* dst = reinterpret_cast<float4*>(
        out + (is_samp ? half_elems : 0) + (long long)bp * 4096);

    #pragma unroll
    for (int it = 0; it < 8; ++it) {
        const int i  = half_tid + it * 128;   // float4 index 0..1023
        const int j  = i >> 4;                // row 0..63
        const int c4 = i & 15;                // float4 col 0..15

        const float hj = hsrc[j];
        float4 vv = v4[c4];
        float4 o;
        o.x = hj * vv.x; o.y = hj * vv.y; o.z = hj * vv.z; o.w = hj * vv.w;
        dst[i] = o;
    }
}

extern "C" void kernel_launch(void* const* d_in, const int* in_sizes, int n_in,
                              void* d_out, int out_size)
{
    const float* x_cat = (const float*)d_in[0];
    const float* noise = (const float*)d_in[1];
    float* out = (float*)d_out;

    const long long half = (long long)out_size / 2;
    const int tiles = in_sizes[0] / 128;   // 8192 (b,p) tiles

    spatial_sampler_kernel<<<tiles, 256>>>(x_cat, noise, out, half);
}